// round 4
// baseline (speedup 1.0000x reference)
#include <cuda_runtime.h>

#define DOUT 128
#define EDIM 16
#define MAX_NODES 100000
#define CAP 64              // bucket capacity per node (deg ~ Poisson(8), max ~35)

// Scratch (device globals — no allocations allowed)
__device__ float g_xw[(size_t)MAX_NODES * DOUT];          // 51.2 MB, L2-resident
__device__ int   g_cnt[MAX_NODES];                        // per-node edge count
__device__ int2  g_elist[(size_t)MAX_NODES * CAP];        // (src, edge_id) buckets

__global__ void zero_cnt_kernel(int n) {
    int i = blockIdx.x * blockDim.x + threadIdx.x;
    if (i < n) g_cnt[i] = 0;
}

// xw = x @ W. 32 rows/block, 256 threads, each thread 4 rows x 4 cols.
__global__ __launch_bounds__(256)
void gemm_xw_kernel(const float* __restrict__ x, const float* __restrict__ W, int n) {
    __shared__ float Ws[DOUT][DOUT];   // 64 KB
    __shared__ float xs[32][DOUT];     // 16 KB
    int tid = threadIdx.x;

    const float4* W4 = (const float4*)W;
    float4* Ws4 = (float4*)Ws;
    #pragma unroll
    for (int i = 0; i < 16; i++) Ws4[tid + i * 256] = W4[tid + i * 256];

    int row0 = blockIdx.x * 32;
    const float4* x4 = (const float4*)(x + (size_t)row0 * DOUT);
    float4* xs4 = (float4*)xs;
    #pragma unroll
    for (int i = 0; i < 4; i++) {
        int idx = tid + i * 256;
        int grow = row0 + (idx >> 5);
        if (grow < n) xs4[idx] = x4[idx];
    }
    __syncthreads();

    int rg = tid >> 5;
    int cg = tid & 31;

    float4 acc0 = {0,0,0,0}, acc1 = {0,0,0,0}, acc2 = {0,0,0,0}, acc3 = {0,0,0,0};
    #pragma unroll 8
    for (int k = 0; k < DOUT; k++) {
        float4 w = *(const float4*)&Ws[k][cg * 4];
        float x0 = xs[rg * 4 + 0][k];
        float x1 = xs[rg * 4 + 1][k];
        float x2 = xs[rg * 4 + 2][k];
        float x3 = xs[rg * 4 + 3][k];
        acc0.x += x0 * w.x; acc0.y += x0 * w.y; acc0.z += x0 * w.z; acc0.w += x0 * w.w;
        acc1.x += x1 * w.x; acc1.y += x1 * w.y; acc1.z += x1 * w.z; acc1.w += x1 * w.w;
        acc2.x += x2 * w.x; acc2.y += x2 * w.y; acc2.z += x2 * w.z; acc2.w += x2 * w.w;
        acc3.x += x3 * w.x; acc3.y += x3 * w.y; acc3.z += x3 * w.z; acc3.w += x3 * w.w;
    }

    float4 accs[4] = {acc0, acc1, acc2, acc3};
    #pragma unroll
    for (int r = 0; r < 4; r++) {
        int grow = row0 + rg * 4 + r;
        if (grow < n)
            *(float4*)&g_xw[(size_t)grow * DOUT + cg * 4] = accs[r];
    }
}

// One thread per edge: append (src, e) to dst's bucket. Int atomics only.
__global__ __launch_bounds__(256)
void scatter_kernel(const int* __restrict__ ei, int nE) {
    int e = blockIdx.x * blockDim.x + threadIdx.x;
    if (e >= nE) return;
    int src = ei[e];
    int dst = ei[nE + e];
    int slot = atomicAdd(&g_cnt[dst], 1);
    if (slot < CAP)
        g_elist[(size_t)dst * CAP + slot] = make_int2(src, e);
}

// One warp per dst node. edge_w held in REGISTERS (16 float4 per lane = its
// 4 output columns) -> zero smem traffic in the edge loop. Inner loop:
// 3 LDG + 16 SHFL + 68 FFMA per edge. FMA-pipe bound (~100us).
__global__ __launch_bounds__(256, 2)
void aggregate_kernel(const float* __restrict__ ea,
                      const float* __restrict__ ew,
                      const float* __restrict__ b,
                      float* __restrict__ out, int n) {
    int tid = threadIdx.x;
    int lane = tid & 31;
    int v = blockIdx.x * 8 + (tid >> 5);
    if (v >= n) return;

    // Per-lane weight slice: ew[k][lane*4 .. lane*4+3] for all 16 k.
    float4 wreg[EDIM];
    #pragma unroll
    for (int k = 0; k < EDIM; k++)
        wreg[k] = *(const float4*)&ew[k * DOUT + lane * 4];

    int deg = g_cnt[v];
    if (deg > CAP) deg = CAP;

    float4 acc = *(const float4*)&b[lane * 4];   // bias folded in

    const int2* bucket = &g_elist[(size_t)v * CAP];
    for (int j = 0; j < deg; j++) {
        int2 se = bucket[j];                     // broadcast load
        float a = (lane < EDIM) ? ea[(size_t)se.y * EDIM + lane] : 0.0f;

        float4 ac = {0,0,0,0};
        #pragma unroll
        for (int k = 0; k < EDIM; k++) {
            float ak = __shfl_sync(0xffffffffu, a, k);
            ac.x += ak * wreg[k].x;
            ac.y += ak * wreg[k].y;
            ac.z += ak * wreg[k].z;
            ac.w += ak * wreg[k].w;
        }

        float4 xv = *(const float4*)&g_xw[(size_t)se.x * DOUT + lane * 4];
        acc.x += ac.x * xv.x;
        acc.y += ac.y * xv.y;
        acc.z += ac.z * xv.z;
        acc.w += ac.w * xv.w;
    }

    *(float4*)&out[(size_t)v * DOUT + lane * 4] = acc;
}

extern "C" void kernel_launch(void* const* d_in, const int* in_sizes, int n_in,
                              void* d_out, int out_size) {
    const float* x  = (const float*)d_in[0];
    const int*   ei = (const int*)d_in[1];
    const float* ea = (const float*)d_in[2];
    const float* W  = (const float*)d_in[3];
    const float* ew = (const float*)d_in[4];
    const float* b  = (const float*)d_in[5];
    float* out = (float*)d_out;

    int n  = in_sizes[0] / DOUT;   // 100000 nodes
    int nE = in_sizes[1] / 2;      // 800000 edges

    zero_cnt_kernel<<<(n + 255) / 256, 256>>>(n);
    gemm_xw_kernel<<<(n + 31) / 32, 256>>>(x, W, n);
    scatter_kernel<<<(nE + 255) / 256, 256>>>(ei, nE);
    aggregate_kernel<<<(n + 7) / 8, 256>>>(ea, ew, b, out, n);
}

// round 5
// speedup vs baseline: 1.2077x; 1.2077x over previous
#include <cuda_runtime.h>

#define DOUT 128
#define EDIM 16
#define MAX_NODES 100000
#define CAP 64              // bucket capacity per node (deg ~ Poisson(8))
#define FULL 0xffffffffu

// Scratch (device globals — no allocations allowed)
__device__ float g_xw[(size_t)MAX_NODES * DOUT];          // 51.2 MB
__device__ int   g_cnt[MAX_NODES];
__device__ int2  g_elist[(size_t)MAX_NODES * CAP];

__global__ void zero_cnt_kernel(int n) {
    int i = blockIdx.x * blockDim.x + threadIdx.x;
    if (i < n) g_cnt[i] = 0;
}

// xw = x @ W. 32 rows/block, 256 threads, each thread 4 rows x 4 cols.
__global__ __launch_bounds__(256)
void gemm_xw_kernel(const float* __restrict__ x, const float* __restrict__ W, int n) {
    __shared__ float Ws[DOUT][DOUT];
    __shared__ float xs[32][DOUT];
    int tid = threadIdx.x;

    const float4* W4 = (const float4*)W;
    float4* Ws4 = (float4*)Ws;
    #pragma unroll
    for (int i = 0; i < 16; i++) Ws4[tid + i * 256] = W4[tid + i * 256];

    int row0 = blockIdx.x * 32;
    const float4* x4 = (const float4*)(x + (size_t)row0 * DOUT);
    float4* xs4 = (float4*)xs;
    #pragma unroll
    for (int i = 0; i < 4; i++) {
        int idx = tid + i * 256;
        int grow = row0 + (idx >> 5);
        if (grow < n) xs4[idx] = x4[idx];
    }
    __syncthreads();

    int rg = tid >> 5;
    int cg = tid & 31;

    float4 acc0 = {0,0,0,0}, acc1 = {0,0,0,0}, acc2 = {0,0,0,0}, acc3 = {0,0,0,0};
    #pragma unroll 8
    for (int k = 0; k < DOUT; k++) {
        float4 w = *(const float4*)&Ws[k][cg * 4];
        float x0 = xs[rg * 4 + 0][k];
        float x1 = xs[rg * 4 + 1][k];
        float x2 = xs[rg * 4 + 2][k];
        float x3 = xs[rg * 4 + 3][k];
        acc0.x += x0 * w.x; acc0.y += x0 * w.y; acc0.z += x0 * w.z; acc0.w += x0 * w.w;
        acc1.x += x1 * w.x; acc1.y += x1 * w.y; acc1.z += x1 * w.z; acc1.w += x1 * w.w;
        acc2.x += x2 * w.x; acc2.y += x2 * w.y; acc2.z += x2 * w.z; acc2.w += x2 * w.w;
        acc3.x += x3 * w.x; acc3.y += x3 * w.y; acc3.z += x3 * w.z; acc3.w += x3 * w.w;
    }

    float4 accs[4] = {acc0, acc1, acc2, acc3};
    #pragma unroll
    for (int r = 0; r < 4; r++) {
        int grow = row0 + rg * 4 + r;
        if (grow < n)
            *(float4*)&g_xw[(size_t)grow * DOUT + cg * 4] = accs[r];
    }
}

// One thread per edge: append (src, e) to dst's bucket. Int atomics only.
__global__ __launch_bounds__(256)
void scatter_kernel(const int* __restrict__ ei, int nE) {
    int e = blockIdx.x * blockDim.x + threadIdx.x;
    if (e >= nE) return;
    int src = ei[e];
    int dst = ei[nE + e];
    int slot = atomicAdd(&g_cnt[dst], 1);
    if (slot < CAP)
        g_elist[(size_t)dst * CAP + slot] = make_int2(src, e);
}

// One warp per dst node. edge_w in registers; bucket batch-loaded in ONE LDG;
// ea + xw prefetched one edge ahead so L2 latency overlaps the shfl/FFMA body.
__global__ __launch_bounds__(256, 2)
void aggregate_kernel(const float* __restrict__ ea,
                      const float* __restrict__ ew,
                      const float* __restrict__ b,
                      float* __restrict__ out, int n) {
    int tid = threadIdx.x;
    int lane = tid & 31;
    int v = blockIdx.x * 8 + (tid >> 5);
    if (v >= n) return;

    // Per-lane weight slice: ew[k][lane*4 .. +3] for all 16 k (64 regs).
    float4 wreg[EDIM];
    #pragma unroll
    for (int k = 0; k < EDIM; k++)
        wreg[k] = *(const float4*)&ew[k * DOUT + lane * 4];

    int deg = g_cnt[v];
    if (deg > CAP) deg = CAP;

    float4 acc = *(const float4*)&b[lane * 4];   // bias folded in

    const int2* bucket = &g_elist[(size_t)v * CAP];
    // Batch bucket load: one LDG covers up to 32 edges (2nd for rare deg>32).
    int2 se_l = (lane < deg) ? bucket[lane] : make_int2(0, 0);
    int2 se_h = (deg > 32 && lane + 32 < deg) ? bucket[lane + 32] : make_int2(0, 0);

    // Prologue: start loads for edge 0.
    float  a_cur = 0.0f;
    float4 xv_cur = {0, 0, 0, 0};
    if (deg > 0) {
        int s0 = __shfl_sync(FULL, se_l.x, 0);
        int e0 = __shfl_sync(FULL, se_l.y, 0);
        a_cur = (lane < EDIM) ? __ldg(&ea[(size_t)e0 * EDIM + lane]) : 0.0f;
        xv_cur = *(const float4*)&g_xw[(size_t)s0 * DOUT + lane * 4];
    }

    for (int j = 0; j < deg; j++) {
        // Prefetch edge j+1 (loads issue before the compute body below).
        float  a_nxt = 0.0f;
        float4 xv_nxt = {0, 0, 0, 0};
        int jn = j + 1;
        if (jn < deg) {
            int sx = (jn < 32) ? se_l.x : se_h.x;
            int sy = (jn < 32) ? se_l.y : se_h.y;
            int sj = __shfl_sync(FULL, sx, jn & 31);
            int ej = __shfl_sync(FULL, sy, jn & 31);
            a_nxt = (lane < EDIM) ? __ldg(&ea[(size_t)ej * EDIM + lane]) : 0.0f;
            xv_nxt = *(const float4*)&g_xw[(size_t)sj * DOUT + lane * 4];
        }

        // Compute edge j: modulate (ea_j @ edge_w) then multiply by xw[src_j].
        float4 ac = {0, 0, 0, 0};
        #pragma unroll
        for (int k = 0; k < EDIM; k++) {
            float ak = __shfl_sync(FULL, a_cur, k);
            ac.x += ak * wreg[k].x;
            ac.y += ak * wreg[k].y;
            ac.z += ak * wreg[k].z;
            ac.w += ak * wreg[k].w;
        }
        acc.x += ac.x * xv_cur.x;
        acc.y += ac.y * xv_cur.y;
        acc.z += ac.z * xv_cur.z;
        acc.w += ac.w * xv_cur.w;

        a_cur = a_nxt;
        xv_cur = xv_nxt;
    }

    *(float4*)&out[(size_t)v * DOUT + lane * 4] = acc;
}

extern "C" void kernel_launch(void* const* d_in, const int* in_sizes, int n_in,
                              void* d_out, int out_size) {
    const float* x  = (const float*)d_in[0];
    const int*   ei = (const int*)d_in[1];
    const float* ea = (const float*)d_in[2];
    const float* W  = (const float*)d_in[3];
    const float* ew = (const float*)d_in[4];
    const float* b  = (const float*)d_in[5];
    float* out = (float*)d_out;

    int n  = in_sizes[0] / DOUT;   // 100000 nodes
    int nE = in_sizes[1] / 2;      // 800000 edges

    zero_cnt_kernel<<<(n + 255) / 256, 256>>>(n);
    gemm_xw_kernel<<<(n + 31) / 32, 256>>>(x, W, n);
    scatter_kernel<<<(nE + 255) / 256, 256>>>(ei, nE);
    aggregate_kernel<<<(n + 7) / 8, 256>>>(ea, ew, b, out, n);
}

// round 6
// speedup vs baseline: 1.5244x; 1.2622x over previous
#include <cuda_runtime.h>

#define DOUT 128
#define EDIM 16
#define MAX_NODES 100000
#define CAP 64
#define FULL 0xffffffffu

typedef unsigned long long u64;

// Scratch (device globals — no allocations allowed)
__device__ float g_xw[(size_t)MAX_NODES * DOUT];
__device__ int   g_cnt[MAX_NODES];
__device__ int2  g_elist[(size_t)MAX_NODES * CAP];

// Packed fp32x2 FMA: d = a*b + c on both halves (ptxas never auto-emits this).
__device__ __forceinline__ u64 ffma2(u64 a, u64 b, u64 c) {
    u64 d;
    asm("fma.rn.f32x2 %0, %1, %2, %3;" : "=l"(d) : "l"(a), "l"(b), "l"(c));
    return d;
}
__device__ __forceinline__ u64 splat2(float v) {
    u64 d;
    asm("mov.b64 %0, {%1, %1};" : "=l"(d) : "f"(v));
    return d;
}

__global__ void zero_cnt_kernel(int n) {
    int i = blockIdx.x * blockDim.x + threadIdx.x;
    if (i < n) g_cnt[i] = 0;
}

// xw = x @ W. 64 rows/block, 256 threads, thread = 8 rows x 4 cols, f32x2 math.
__global__ __launch_bounds__(256)
void gemm_xw_kernel(const float* __restrict__ x, const float* __restrict__ W, int n) {
    __shared__ float Ws[DOUT][DOUT];   // 64 KB
    __shared__ float xs[64][DOUT];     // 32 KB
    int tid = threadIdx.x;

    const float4* W4 = (const float4*)W;
    float4* Ws4 = (float4*)Ws;
    #pragma unroll
    for (int i = 0; i < 16; i++) Ws4[tid + i * 256] = W4[tid + i * 256];

    int row0 = blockIdx.x * 64;
    const float4* x4 = (const float4*)(x + (size_t)row0 * DOUT);
    float4* xs4 = (float4*)xs;
    #pragma unroll
    for (int i = 0; i < 8; i++) {
        int idx = tid + i * 256;              // 64*32 = 2048 float4
        int grow = row0 + (idx >> 5);
        if (grow < n) xs4[idx] = x4[idx];
    }
    __syncthreads();

    int rg = tid >> 5;        // warp -> rows rg*8 .. rg*8+7
    int cg = tid & 31;        // lane -> cols cg*4 .. cg*4+3

    u64 acc[8][2];
    #pragma unroll
    for (int r = 0; r < 8; r++) { acc[r][0] = 0ULL; acc[r][1] = 0ULL; }

    #pragma unroll 4
    for (int k = 0; k < DOUT; k += 2) {
        // w rows k and k+1, this lane's 4 cols, as f32x2 pairs
        const u64* wa = (const u64*)&Ws[k][cg * 4];
        const u64* wb = (const u64*)&Ws[k + 1][cg * 4];
        u64 wa0 = wa[0], wa1 = wa[1];
        u64 wb0 = wb[0], wb1 = wb[1];
        #pragma unroll
        for (int r = 0; r < 8; r++) {
            float2 xp = *(const float2*)&xs[rg * 8 + r][k];   // LDS.64 broadcast
            u64 xk0 = splat2(xp.x);
            u64 xk1 = splat2(xp.y);
            acc[r][0] = ffma2(xk0, wa0, acc[r][0]);
            acc[r][1] = ffma2(xk0, wa1, acc[r][1]);
            acc[r][0] = ffma2(xk1, wb0, acc[r][0]);
            acc[r][1] = ffma2(xk1, wb1, acc[r][1]);
        }
    }

    #pragma unroll
    for (int r = 0; r < 8; r++) {
        int grow = row0 + rg * 8 + r;
        if (grow < n) {
            u64* dst = (u64*)&g_xw[(size_t)grow * DOUT + cg * 4];
            dst[0] = acc[r][0];
            dst[1] = acc[r][1];
        }
    }
}

// One thread per edge: append (src, e) to dst's bucket. Int atomics only.
__global__ __launch_bounds__(256)
void scatter_kernel(const int* __restrict__ ei, int nE) {
    int e = blockIdx.x * blockDim.x + threadIdx.x;
    if (e >= nE) return;
    int src = ei[e];
    int dst = ei[nE + e];
    int slot = atomicAdd(&g_cnt[dst], 1);
    if (slot < CAP)
        g_elist[(size_t)dst * CAP + slot] = make_int2(src, e);
}

// One warp per dst node. edge_w in registers (f32x2 pairs). TWO edges per
// iteration: independent chains for ILP, all math as FFMA2.
__global__ __launch_bounds__(256, 2)
void aggregate_kernel(const float* __restrict__ ea,
                      const float* __restrict__ ew,
                      const float* __restrict__ b,
                      float* __restrict__ out, int n) {
    int tid = threadIdx.x;
    int lane = tid & 31;
    int v = blockIdx.x * 8 + (tid >> 5);
    if (v >= n) return;

    // Per-lane weight slice as f32x2 pairs: ew[k][lane*4 .. +3], 32 u64 regs.
    u64 wp[EDIM][2];
    #pragma unroll
    for (int k = 0; k < EDIM; k++) {
        const u64* w = (const u64*)&ew[k * DOUT + lane * 4];
        wp[k][0] = w[0];
        wp[k][1] = w[1];
    }

    int deg = g_cnt[v];
    if (deg > CAP) deg = CAP;

    const u64* b2 = (const u64*)&b[lane * 4];
    u64 acc0 = b2[0], acc1 = b2[1];            // bias folded in

    const int2* bucket = &g_elist[(size_t)v * CAP];
    int2 se_l = (lane < deg) ? bucket[lane] : make_int2(0, 0);
    int2 se_h = (deg > 32 && lane + 32 < deg) ? bucket[lane + 32] : make_int2(0, 0);

    for (int j = 0; j < deg; j += 2) {
        bool hi = (j >= 32);
        int m = j & 31;
        int s0 = __shfl_sync(FULL, hi ? se_h.x : se_l.x, m);
        int e0 = __shfl_sync(FULL, hi ? se_h.y : se_l.y, m);
        int s1 = __shfl_sync(FULL, hi ? se_h.x : se_l.x, m + 1);
        int e1 = __shfl_sync(FULL, hi ? se_h.y : se_l.y, m + 1);
        bool v1 = (j + 1 < deg);

        // Independent loads for both edges (L2-resident)
        float a0 = (lane < EDIM) ? __ldg(&ea[(size_t)e0 * EDIM + lane]) : 0.0f;
        float a1 = (v1 && lane < EDIM) ? __ldg(&ea[(size_t)e1 * EDIM + lane]) : 0.0f;
        const u64* x0 = (const u64*)&g_xw[(size_t)s0 * DOUT + lane * 4];
        const u64* x1 = (const u64*)&g_xw[(size_t)s1 * DOUT + lane * 4];
        u64 xv00 = x0[0], xv01 = x0[1];
        u64 xv10 = x1[0], xv11 = x1[1];

        u64 ac00 = 0, ac01 = 0, ac10 = 0, ac11 = 0;
        #pragma unroll
        for (int k = 0; k < EDIM; k++) {
            u64 ak0 = splat2(__shfl_sync(FULL, a0, k));
            u64 ak1 = splat2(__shfl_sync(FULL, a1, k));
            ac00 = ffma2(ak0, wp[k][0], ac00);
            ac01 = ffma2(ak0, wp[k][1], ac01);
            ac10 = ffma2(ak1, wp[k][0], ac10);
            ac11 = ffma2(ak1, wp[k][1], ac11);
        }

        acc0 = ffma2(ac00, xv00, acc0);
        acc1 = ffma2(ac01, xv01, acc1);
        acc0 = ffma2(ac10, xv10, acc0);   // a1==0 when invalid -> ac1==0 -> no-op
        acc1 = ffma2(ac11, xv11, acc1);
    }

    u64* op = (u64*)&out[(size_t)v * DOUT + lane * 4];
    op[0] = acc0;
    op[1] = acc1;
}

extern "C" void kernel_launch(void* const* d_in, const int* in_sizes, int n_in,
                              void* d_out, int out_size) {
    const float* x  = (const float*)d_in[0];
    const int*   ei = (const int*)d_in[1];
    const float* ea = (const float*)d_in[2];
    const float* W  = (const float*)d_in[3];
    const float* ew = (const float*)d_in[4];
    const float* b  = (const float*)d_in[5];
    float* out = (float*)d_out;

    int n  = in_sizes[0] / DOUT;   // 100000 nodes
    int nE = in_sizes[1] / 2;      // 800000 edges

    zero_cnt_kernel<<<(n + 255) / 256, 256>>>(n);
    gemm_xw_kernel<<<(n + 63) / 64, 256>>>(x, W, n);
    scatter_kernel<<<(nE + 255) / 256, 256>>>(ei, nE);
    aggregate_kernel<<<(n + 7) / 8, 256>>>(ea, ew, b, out, n);
}